// round 17
// baseline (speedup 1.0000x reference)
#include <cuda_runtime.h>
#include <cuda_bf16.h>
#include <math.h>
#include <stdint.h>

// ---------------------------------------------------------------------------
// Problem constants
// ---------------------------------------------------------------------------
#define SEQ_LEN   8
#define FEAT      2048
#define DOUT      1152
#define WAY       5
#define SHOT      5
#define NQ        500
#define T_LEN     28
#define N_SUP     (WAY * SHOT)           // 25
#define N_CLIPS   (N_SUP + NQ)           // 525
#define N_FRAMES  (N_CLIPS * SEQ_LEN)    // 4200
#define WCOLS     (4 * DOUT)             // 4608
#define SROWS     (N_SUP * T_LEN)        // 700
#define QROWS     (NQ * T_LEN)           // 14000
#define KU        (SHOT * T_LEN)         // 140
#define KUP       144                    // KU padded to 16B-aligned bf16 rows
#define LN_EPS    1e-5f

// bf16 mma tile config
#define BM 128
#define BN 128
#define BK 64
#define PADH 72                                  // smem row stride (halves)
#define STG_HALFS ((BM + BN) * PADH)             // 18432 halves / stage
#define SM_TOTAL (2 * STG_HALFS * 2)             // 2 stages -> 73728 bytes

__constant__ int2 c_tup[T_LEN] = {
    {0,1},{0,2},{0,3},{0,4},{0,5},{0,6},{0,7},
    {1,2},{1,3},{1,4},{1,5},{1,6},{1,7},
    {2,3},{2,4},{2,5},{2,6},{2,7},
    {3,4},{3,5},{3,6},{3,7},
    {4,5},{4,6},{4,7},
    {5,6},{5,7},
    {6,7}
};

// ---------------------------------------------------------------------------
// Device scratch (allocation-free per harness rules)
// ---------------------------------------------------------------------------
__device__ float          g_PE[SEQ_LEN * FEAT];
__device__ __nv_bfloat16  g_X[N_FRAMES * FEAT];          // frames + PE
__device__ __nv_bfloat16  g_WT[WCOLS * FEAT];            // packed W, K-major
__device__ float          g_P[N_FRAMES * WCOLS];         // frame partials (fp32)
__device__ __nv_bfloat16  g_sk[SROWS * DOUT];            // support K (LN'd)
__device__ __nv_bfloat16  g_svT[WAY * DOUT * KUP];       // support V^T, padded rows
__device__ __nv_bfloat16  g_qk[QROWS * DOUT];            // query K (LN'd)
__device__ float          g_qv[QROWS * DOUT];            // query V (fp32)
__device__ float          g_S[QROWS * SROWS];            // scores (fp32)
__device__ __nv_bfloat16  g_attn[WAY * QROWS * KUP];     // attn per-class planes
__device__ float          g_dist[WAY * NQ];

// ---------------------------------------------------------------------------
// PTX helpers (baseline ISA only -- harness targets compute_103, no tcgen05)
// ---------------------------------------------------------------------------
__device__ __forceinline__ uint32_t smem_u32(const void* p) {
    uint32_t a;
    asm("{ .reg .u64 t; cvta.to.shared.u64 t, %1; cvt.u32.u64 %0, t; }" : "=r"(a) : "l"(p));
    return a;
}
__device__ __forceinline__ void cp_async16(uint32_t dst, const void* src, int sz) {
    asm volatile("cp.async.cg.shared.global [%0], [%1], 16, %2;"
                 :: "r"(dst), "l"(src), "r"(sz) : "memory");
}
__device__ __forceinline__ void cp_commit() {
    asm volatile("cp.async.commit_group;" ::: "memory");
}
template<int N>
__device__ __forceinline__ void cp_wait() {
    asm volatile("cp.async.wait_group %0;" :: "n"(N) : "memory");
}
__device__ __forceinline__ void ldmx4(uint32_t& r0, uint32_t& r1, uint32_t& r2,
                                      uint32_t& r3, uint32_t addr) {
    asm volatile("ldmatrix.sync.aligned.m8n8.x4.shared.b16 {%0,%1,%2,%3}, [%4];"
                 : "=r"(r0), "=r"(r1), "=r"(r2), "=r"(r3) : "r"(addr));
}

// D += A@B, one m16n8k16 bf16 tile (fp32 accumulate)
__device__ __forceinline__ void mma_bf16(float* c, const uint32_t* a, const uint32_t* b) {
    asm volatile(
        "mma.sync.aligned.m16n8k16.row.col.f32.bf16.bf16.f32 "
        "{%0,%1,%2,%3}, {%4,%5,%6,%7}, {%8,%9}, {%0,%1,%2,%3};"
        : "+f"(c[0]), "+f"(c[1]), "+f"(c[2]), "+f"(c[3])
        : "r"(a[0]), "r"(a[1]), "r"(a[2]), "r"(a[3]), "r"(b[0]), "r"(b[1]));
}

// ---------------------------------------------------------------------------
// K0pe: positional-encoding table [8, 2048]
// ---------------------------------------------------------------------------
__global__ void pe_kernel()
{
    int idx = blockIdx.x * blockDim.x + threadIdx.x;
    if (idx >= SEQ_LEN * FEAT) return;
    int d = idx & (FEAT - 1);
    int f = idx >> 11;
    const float c = -9.210340371976184f / 2048.0f;
    int  i2  = d >> 1;
    float dv = expf((float)(2 * i2) * c);
    float arg = (float)f * dv;
    g_PE[idx] = (d & 1) ? cosf(arg) : sinf(arg);
}

// ---------------------------------------------------------------------------
// K0a: X = frames + PE (bf16)
// ---------------------------------------------------------------------------
__global__ void pack_x_kernel(const float* __restrict__ sup,
                              const float* __restrict__ qry)
{
    int idx = blockIdx.x * blockDim.x + threadIdx.x;
    if (idx >= N_FRAMES * FEAT) return;
    int d   = idx & (FEAT - 1);
    int row = idx >> 11;
    int f   = row & 7;
    float pe = g_PE[f * FEAT + d];
    float x = (row < N_SUP * SEQ_LEN) ? sup[idx] : qry[idx - N_SUP * SEQ_LEN * FEAT];
    g_X[idx] = __float2bfloat16_rn(x + pe);
}

// ---------------------------------------------------------------------------
// K0b: WT[n,k] = W_packed[k,n], tiled transpose -> bf16
// ---------------------------------------------------------------------------
__global__ void pack_wt_kernel(const float* __restrict__ kw,
                               const float* __restrict__ vw)
{
    __shared__ float t[32][33];
    int n0 = blockIdx.x * 32;
    int k0 = blockIdx.y * 32;
    int tx = threadIdx.x, ty = threadIdx.y;   // 32x8

    int blk = n0 / DOUT;
    const float* src = (blk < 2) ? kw : vw;
    int half = blk & 1;
    int jj0  = n0 - blk * DOUT;

#pragma unroll
    for (int i = 0; i < 4; i++) {
        int k = k0 + ty + i * 8;
        t[ty + i * 8][tx] = src[(size_t)(half * FEAT + k) * DOUT + jj0 + tx];
    }
    __syncthreads();
#pragma unroll
    for (int i = 0; i < 4; i++) {
        int n = n0 + ty + i * 8;
        g_WT[(size_t)n * FEAT + k0 + tx] = __float2bfloat16_rn(t[tx][ty + i * 8]);
    }
}

// zero g_dist + entire g_svT (so KUP pads stay zero; combine writes real cols)
#define SVT_ELEMS (WAY * DOUT * KUP)
__global__ void zero_kernel()
{
    int idx = blockIdx.x * blockDim.x + threadIdx.x;
    if (idx < WAY * NQ) g_dist[idx] = 0.0f;
    if (idx < SVT_ELEMS) g_svT[idx] = __float2bfloat16_rn(0.0f);
}

// ---------------------------------------------------------------------------
// bf16 mma.sync GEMM: C[M,N] = A[M,K] @ B[N,K]^T (both K-major bf16).
// 128x128x64 block tile, 8 warps (4M x 2N), warp tile 32x64, 2-stage cp.async,
// ldmatrix.x4 fragment loads (6 per k16 slice instead of 24 LDS.32).
// MODE 0: store C (fp32).  MODE 1: store C*scale w/ col guard.
// MODE 2: fused (qv-C)^2 row-reduction -> atomicAdd g_dist.
//         Grid decode: MODE 2 puts class in blockIdx.x (fastest) so the 5
//         class-CTAs sharing one qv tile run consecutively -> qv stays in L2.
// ---------------------------------------------------------------------------
template<int MODE>
__global__ void __launch_bounds__(256, 2)
mma_gemm(const __nv_bfloat16* __restrict__ Ain, const __nv_bfloat16* __restrict__ Bin,
         float* __restrict__ C, int M, int N, int K,
         int lda, int ldb, int ldc, float scale)
{
    extern __shared__ __nv_bfloat16 sm[];
    int tid  = threadIdx.x;
    int wid  = tid >> 5, lane = tid & 31;
    int gid  = lane >> 2, tig = lane & 3;
    int wy   = wid & 3,  wx  = wid >> 2;

    int mBase, nBase, cls = 0;
    const __nv_bfloat16* A = Ain;
    const __nv_bfloat16* B = Bin;
    if (MODE == 2) {
        cls   = blockIdx.x;                   // fastest -> qv-tile L2 reuse
        nBase = blockIdx.y * BN;
        mBase = blockIdx.z * BM;
        A += (size_t)cls * QROWS * KUP;       // attn plane, lda = KUP
        B += (size_t)cls * DOUT * KUP;        // svT class block, ldb = KUP
    } else {
        nBase = blockIdx.x * BN;
        mBase = blockIdx.y * BM;
    }

    float acc[2][8][4];
#pragma unroll
    for (int i = 0; i < 2; i++)
#pragma unroll
        for (int j = 0; j < 8; j++)
#pragma unroll
            for (int l = 0; l < 4; l++) acc[i][j][l] = 0.f;

    const int nIter = (K + BK - 1) / BK;
    uint32_t sbase = smem_u32(sm);

    // ldmatrix address offsets (bytes, within a stage)
    int lq = lane >> 3, lr = lane & 7;
    uint32_t aOff[2], bOff[4];
#pragma unroll
    for (int mt = 0; mt < 2; mt++)
        aOff[mt] = (uint32_t)(((wy * 32 + mt * 16 + (lq & 1) * 8 + lr) * PADH
                               + (lq >> 1) * 8) * 2);
#pragma unroll
    for (int j = 0; j < 4; j++)
        bOff[j] = (uint32_t)((BM * PADH + (wx * 64 + j * 16 + (lq >> 1) * 8 + lr) * PADH
                              + (lq & 1) * 8) * 2);

    // stage loader: A tile [128 x 64] + B tile [128 x 64] bf16, 16B cp.async
    auto load_stage = [&](int it, int s) {
        int k0 = it * BK;
        uint32_t stg = sbase + (uint32_t)s * (STG_HALFS * 2);
#pragma unroll
        for (int p = 0; p < 4; p++) {
            int i = tid + p * 256;
            int r = i >> 3, seg = i & 7;
            int gr = mBase + r, gk = k0 + seg * 8;
            int ok = (gr < M) & (gk < K);
            const __nv_bfloat16* src = ok ? (A + (size_t)gr * lda + gk) : A;
            cp_async16(stg + (uint32_t)(r * PADH + seg * 8) * 2, src, ok ? 16 : 0);
        }
#pragma unroll
        for (int p = 0; p < 4; p++) {
            int i = tid + p * 256;
            int r = i >> 3, seg = i & 7;
            int gn = nBase + r, gk = k0 + seg * 8;
            int ok = (gn < N) & (gk < K);
            const __nv_bfloat16* src = ok ? (B + (size_t)gn * ldb + gk) : B;
            cp_async16(stg + (uint32_t)(BM * PADH + r * PADH + seg * 8) * 2, src, ok ? 16 : 0);
        }
        cp_commit();
    };

    load_stage(0, 0);

    for (int it = 0; it < nIter; it++) {
        bool more = (it + 1 < nIter);
        if (more) load_stage(it + 1, (it + 1) & 1);
        if (more) cp_wait<1>(); else cp_wait<0>();
        __syncthreads();

        uint32_t stg = sbase + (uint32_t)(it & 1) * (STG_HALFS * 2);

#pragma unroll
        for (int kk = 0; kk < BK; kk += 16) {
            uint32_t af[2][4];
            uint32_t bf[8][2];
#pragma unroll
            for (int mt = 0; mt < 2; mt++)
                ldmx4(af[mt][0], af[mt][1], af[mt][2], af[mt][3],
                      stg + aOff[mt] + kk * 2);
#pragma unroll
            for (int j = 0; j < 4; j++)
                ldmx4(bf[2 * j][0], bf[2 * j][1], bf[2 * j + 1][0], bf[2 * j + 1][1],
                      stg + bOff[j] + kk * 2);
#pragma unroll
            for (int mt = 0; mt < 2; mt++)
#pragma unroll
                for (int nt = 0; nt < 8; nt++)
                    mma_bf16(acc[mt][nt], af[mt], bf[nt]);
        }
        __syncthreads();
    }

    // ------------------------------------------------------------ epilogue
    if (MODE == 2) {
        float* rowsum = (float*)sm;               // reuse smem (post-sync)
        if (tid < BM) rowsum[tid] = 0.f;
        __syncthreads();
#pragma unroll
        for (int mt = 0; mt < 2; mt++) {
#pragma unroll
            for (int h = 0; h < 2; h++) {
                int rloc = wy * 32 + mt * 16 + gid + 8 * h;
                int gr = mBase + rloc;
                if (gr < M) {
                    float s = 0.f;
#pragma unroll
                    for (int nt = 0; nt < 8; nt++) {
                        int gc = nBase + wx * 64 + nt * 8 + tig * 2;
                        float2 q = *(const float2*)(g_qv + (size_t)gr * DOUT + gc);
                        float d0 = q.x - acc[mt][nt][2 * h];
                        float d1 = q.y - acc[mt][nt][2 * h + 1];
                        s += d0 * d0 + d1 * d1;
                    }
                    atomicAdd(&rowsum[rloc], s);
                }
            }
        }
        __syncthreads();
        if (tid < BM) {
            int gr = mBase + tid;
            if (gr < M) atomicAdd(&g_dist[cls * NQ + gr / T_LEN], rowsum[tid]);
        }
    } else {
#pragma unroll
        for (int mt = 0; mt < 2; mt++) {
#pragma unroll
            for (int h = 0; h < 2; h++) {
                int gr = mBase + wy * 32 + mt * 16 + gid + 8 * h;
                if (gr >= M) continue;
                float* crow = C + (size_t)gr * ldc;
#pragma unroll
                for (int nt = 0; nt < 8; nt++) {
                    int gc = nBase + wx * 64 + nt * 8 + tig * 2;
                    if (MODE == 1 && gc >= N) continue;  // N even, pair-safe
                    float2 v;
                    v.x = acc[mt][nt][2 * h] * scale;
                    v.y = acc[mt][nt][2 * h + 1] * scale;
                    *(float2*)(crow + gc) = v;
                }
            }
        }
    }
}

// ---------------------------------------------------------------------------
// K2: combine frame partials + bias; LN on K path (outputs bf16; qv fp32).
// ---------------------------------------------------------------------------
__global__ void __launch_bounds__(256)
combine_ln_kernel(const float* __restrict__ kb, const float* __restrict__ vb,
                  const float* __restrict__ gamma, const float* __restrict__ beta)
{
    __shared__ float buf[DOUT];
    __shared__ float rs[8], rq[8];

    int r = blockIdx.x;
    int n = r / T_LEN;
    int t = r - n * T_LEN;
    int2 tp = c_tup[t];

    const float* pi = g_P + (size_t)(n * SEQ_LEN + tp.x) * WCOLS;
    const float* pj = g_P + (size_t)(n * SEQ_LEN + tp.y) * WCOLS;

    __nv_bfloat16* kout;
    float* qvout = nullptr;
    __nv_bfloat16* svTout = nullptr;
    if (n < N_SUP) {
        kout = g_sk + (size_t)r * DOUT;
        int c  = n / SHOT;
        int ku = (n - c * SHOT) * T_LEN + t;
        svTout = g_svT + (size_t)c * DOUT * KUP + ku;    // + d*KUP per element
    } else {
        size_t qr = (size_t)(r - SROWS) * DOUT;
        kout  = g_qk + qr;
        qvout = g_qv + qr;
    }

    int tid = threadIdx.x;
    float s = 0.f, sq = 0.f;
    for (int d = tid; d < DOUT; d += 256) {
        float kv = pi[d] + pj[DOUT + d] + kb[d];
        buf[d] = kv;
        s += kv; sq += kv * kv;
        float vv = pi[2 * DOUT + d] + pj[3 * DOUT + d] + vb[d];
        if (qvout) qvout[d] = vv;
        else       svTout[(size_t)d * KUP] = __float2bfloat16_rn(vv);
    }
#pragma unroll
    for (int o = 16; o; o >>= 1) {
        s  += __shfl_xor_sync(0xffffffffu, s, o);
        sq += __shfl_xor_sync(0xffffffffu, sq, o);
    }
    int lane = tid & 31, wid = tid >> 5;
    if (lane == 0) { rs[wid] = s; rq[wid] = sq; }
    __syncthreads();
    if (tid == 0) {
        float S = 0.f, Q = 0.f;
#pragma unroll
        for (int w = 0; w < 8; w++) { S += rs[w]; Q += rq[w]; }
        rs[0] = S; rq[0] = Q;
    }
    __syncthreads();
    float mean = rs[0] * (1.0f / DOUT);
    float var  = rq[0] * (1.0f / DOUT) - mean * mean;
    float rstd = rsqrtf(var + LN_EPS);
    for (int d = tid; d < DOUT; d += 256)
        kout[d] = __float2bfloat16_rn((buf[d] - mean) * rstd * gamma[d] + beta[d]);
}

// ---------------------------------------------------------------------------
// K4: softmax over 140-chunks; writes bf16 attn into per-class planes
// (row stride KUP=144, pads [140,144) zeroed for the proto GEMM).
// ---------------------------------------------------------------------------
__global__ void softmax_kernel()
{
    int warp = (blockIdx.x * blockDim.x + threadIdx.x) >> 5;
    if (warp >= QROWS * WAY) return;
    int lane = threadIdx.x & 31;
    int row = warp / WAY;
    int c   = warp - row * WAY;
    const float* p = g_S + (size_t)row * SROWS + c * KU;
    __nv_bfloat16* po = g_attn + ((size_t)c * QROWS + row) * KUP;

    float v[5];
    float mx = -1e30f;
#pragma unroll
    for (int l = 0; l < 5; l++) {
        int idx = lane + 32 * l;
        v[l] = (idx < KU) ? p[idx] : -1e30f;
        mx = fmaxf(mx, v[l]);
    }
#pragma unroll
    for (int o = 16; o; o >>= 1) mx = fmaxf(mx, __shfl_xor_sync(0xffffffffu, mx, o));
    float s = 0.f;
#pragma unroll
    for (int l = 0; l < 5; l++) {
        int idx = lane + 32 * l;
        v[l] = (idx < KU) ? expf(v[l] - mx) : 0.f;
        s += v[l];
    }
#pragma unroll
    for (int o = 16; o; o >>= 1) s += __shfl_xor_sync(0xffffffffu, s, o);
    float inv = 1.0f / s;
#pragma unroll
    for (int l = 0; l < 5; l++) {
        int idx = lane + 32 * l;
        if (idx < KU)       po[idx] = __float2bfloat16_rn(v[l] * inv);
        else if (idx < KUP) po[idx] = __float2bfloat16_rn(0.0f);
    }
}

// ---------------------------------------------------------------------------
// K6: logits[q, c]
// ---------------------------------------------------------------------------
__global__ void final_kernel(const float* __restrict__ gt,
                             const float* __restrict__ tw,
                             float* __restrict__ out)
{
    int idx = blockIdx.x * blockDim.x + threadIdx.x;
    if (idx >= NQ * WAY) return;
    int q = idx / WAY;
    int c = idx - q * WAY;
    out[idx] = -(g_dist[c * NQ + q] * (1.0f / T_LEN)) * gt[0] * tw[0];
}

// ---------------------------------------------------------------------------
// launcher
// ---------------------------------------------------------------------------
extern "C" void kernel_launch(void* const* d_in, const int* in_sizes, int n_in,
                              void* d_out, int out_size)
{
    const float* sup   = (const float*)d_in[0];
    // d_in[1] = support_labels (sorted & balanced -> implicit reshape)
    const float* qry   = (const float*)d_in[2];
    const float* kw    = (const float*)d_in[3];
    const float* kb    = (const float*)d_in[4];
    const float* vw    = (const float*)d_in[5];
    const float* vb    = (const float*)d_in[6];
    const float* gamma = (const float*)d_in[7];
    const float* beta  = (const float*)d_in[8];
    const float* gt    = (const float*)d_in[9];
    const float* tw    = (const float*)d_in[10];
    float* out = (float*)d_out;

    __nv_bfloat16 *pX, *pWT, *pSK, *pSVT, *pQK, *pAT;
    float *pP, *pS;
    cudaGetSymbolAddress((void**)&pX,  g_X);
    cudaGetSymbolAddress((void**)&pWT, g_WT);
    cudaGetSymbolAddress((void**)&pP,  g_P);
    cudaGetSymbolAddress((void**)&pSK, g_sk);
    cudaGetSymbolAddress((void**)&pSVT, g_svT);
    cudaGetSymbolAddress((void**)&pQK, g_qk);
    cudaGetSymbolAddress((void**)&pS,  g_S);
    cudaGetSymbolAddress((void**)&pAT, g_attn);

    static bool attr_done = false;
    if (!attr_done) {
        cudaFuncSetAttribute(mma_gemm<0>, cudaFuncAttributeMaxDynamicSharedMemorySize, SM_TOTAL);
        cudaFuncSetAttribute(mma_gemm<1>, cudaFuncAttributeMaxDynamicSharedMemorySize, SM_TOTAL);
        cudaFuncSetAttribute(mma_gemm<2>, cudaFuncAttributeMaxDynamicSharedMemorySize, SM_TOTAL);
        attr_done = true;
    }

    pe_kernel<<<(SEQ_LEN * FEAT + 255) / 256, 256>>>();
    pack_x_kernel<<<(N_FRAMES * FEAT + 255) / 256, 256>>>(sup, qry);
    pack_wt_kernel<<<dim3(WCOLS / 32, FEAT / 32), dim3(32, 8)>>>(kw, vw);
    zero_kernel<<<(SVT_ELEMS + 255) / 256, 256>>>();

    // frame partials: [4200,2048] @ [4608,2048]^T -> fp32
    mma_gemm<0><<<dim3(WCOLS / BN, (N_FRAMES + BM - 1) / BM), 256, SM_TOTAL>>>(
        pX, pWT, pP, N_FRAMES, WCOLS, FEAT, FEAT, FEAT, WCOLS, 1.0f);

    combine_ln_kernel<<<N_CLIPS * T_LEN, 256>>>(kb, vb, gamma, beta);

    // scores: [14000,1152] @ [700,1152]^T, scaled by 1/sqrt(1152) -> fp32
    mma_gemm<1><<<dim3((SROWS + BN - 1) / BN, (QROWS + BM - 1) / BM), 256, SM_TOTAL>>>(
        pQK, pSK, pS, QROWS, SROWS, DOUT, DOUT, DOUT, SROWS,
        0.029462782549439484f);

    softmax_kernel<<<(QROWS * WAY * 32 + 255) / 256, 256>>>();

    // proto + fused distance: per class, attn[14000,144] @ svT[1152,144]^T
    // class in grid.x (fastest) -> the 5 CTAs sharing a qv tile are adjacent
    mma_gemm<2><<<dim3(WAY, DOUT / BN, (QROWS + BM - 1) / BM), 256, SM_TOTAL>>>(
        pAT, pSVT, nullptr, QROWS, DOUT, KUP, KUP, KUP, 0, 1.0f);

    final_kernel<<<(NQ * WAY + 255) / 256, 256>>>(gt, tw, out);
}